// round 5
// baseline (speedup 1.0000x reference)
#include <cuda_runtime.h>

// PermuteWeightSharing: out[..., i*16+k] = x[..., p[i]*16+k] - x[..., n[i]*16+k]
// x: (512,16,16,256) fp32 = 131072 rows x 256 floats (64 x 16B chunks, 16 slots of 64B).
//
// R3: one warp per row, row held as v0=chunk[lane], v1=chunk[lane+32].
// The 64-chunk permutation (2 chunks per lane) forms a 2-regular bipartite
// multigraph src-lane -> dst-lane; it decomposes into 2 perfect matchings.
// Pre-select (ALU) at the source puts the matching-0 chunk in r0, matching-1
// in r1; ONE shfl per register per operand then delivers everything:
// 16 shfl/row total (information floor) vs 32 before. Loads/stores stay
// fully coalesced. Routing tables built once by a tiny setup kernel.

#define FULLMASK 0xFFFFFFFFu

__device__ int d_route[32];   // packed per-lane routing (pos in low 16b, neg in high 16b)

// ---------------------------------------------------------------------------
// Setup: decode one-hot perms, 2-color the slot-level routing multigraph
// (edges = 16 out-slots; dst-partner(i) = i^8, src-partner(i) = Pinv[P[i]^8]),
// emit per-lane packed route words.
// ---------------------------------------------------------------------------
__global__ void route_setup(const float* __restrict__ Ppos,
                            const float* __restrict__ Pneg)
{
    __shared__ int P[2][16], Pinv[2][16], col[2][16];
    int t = threadIdx.x;              // 32 threads

    if (t < 32) {
        int o = t >> 4, i = t & 15;
        const float* M = o ? Pneg : Ppos;
        int js = 0;
        #pragma unroll
        for (int j = 0; j < 16; ++j)
            if (M[i * 16 + j] > 0.5f) js = j;
        P[o][i] = js;                 // out slot i sources from in slot js
    }
    __syncthreads();
    if (t < 32) { int o = t >> 4, i = t & 15; Pinv[o][P[o][i]] = i; }
    __syncthreads();

    if (t < 2) {                      // one thread per operand: cycle walk
        int o = t;
        for (int i = 0; i < 16; ++i) col[o][i] = -1;
        for (int st = 0; st < 16; ++st) {
            if (col[o][st] >= 0) continue;
            int e = st, c = 0;
            while (col[o][e] < 0) {
                col[o][e] = c;        // edge e gets color c
                int f = e ^ 8;        // dst partner: opposite color
                col[o][f] = 1 - c;
                e = Pinv[o][P[o][f] ^ 8];   // src partner of f: color c again
            }
        }
    }
    __syncthreads();

    if (t < 32) {
        int l = t, g = l >> 2, k = l & 3;
        unsigned rt = 0;
        #pragma unroll
        for (int o = 0; o < 2; ++o) {
            int ilo = g, ihi = g + 8;
            int c_lo = col[o][ilo];               // colors of lo/hi edges differ
            int i0 = (c_lo == 0) ? ilo : ihi;     // this dst lane's color-0 edge
            int i1 = (c_lo == 0) ? ihi : ilo;
            int src1 = 4 * (P[o][i0] & 7) + k;    // src lane for matching 0
            int src2 = 4 * (P[o][i1] & 7) + k;    // src lane for matching 1
            int swp  = c_lo;                      // 1: matching-0 delivers hi
            int sel  = col[o][Pinv[o][g]];        // 1: this lane's color-0 chunk is v1
            rt |= (unsigned)(src1 | (src2 << 5) | (sel << 10) | (swp << 11)) << (16 * o);
        }
        d_route[l] = (int)rt;
    }
}

// ---------------------------------------------------------------------------
// Main kernel
// ---------------------------------------------------------------------------
__device__ __forceinline__ void route_gather(
    const float4 v0, const float4 v1,
    int s1, int s2, unsigned sel, unsigned swp,
    float4& lo, float4& hi)
{
    float4 r0, r1;                                // source-side pre-select (ALU)
    r0.x = sel ? v1.x : v0.x;   r1.x = sel ? v0.x : v1.x;
    r0.y = sel ? v1.y : v0.y;   r1.y = sel ? v0.y : v1.y;
    r0.z = sel ? v1.z : v0.z;   r1.z = sel ? v0.z : v1.z;
    r0.w = sel ? v1.w : v0.w;   r1.w = sel ? v0.w : v1.w;

    float4 t1, t2;                                // one shfl per register
    t1.x = __shfl_sync(FULLMASK, r0.x, s1);
    t1.y = __shfl_sync(FULLMASK, r0.y, s1);
    t1.z = __shfl_sync(FULLMASK, r0.z, s1);
    t1.w = __shfl_sync(FULLMASK, r0.w, s1);
    t2.x = __shfl_sync(FULLMASK, r1.x, s2);
    t2.y = __shfl_sync(FULLMASK, r1.y, s2);
    t2.z = __shfl_sync(FULLMASK, r1.z, s2);
    t2.w = __shfl_sync(FULLMASK, r1.w, s2);

    lo.x = swp ? t2.x : t1.x;   hi.x = swp ? t1.x : t2.x;   // dst-side post-select
    lo.y = swp ? t2.y : t1.y;   hi.y = swp ? t1.y : t2.y;
    lo.z = swp ? t2.z : t1.z;   hi.z = swp ? t1.z : t2.z;
    lo.w = swp ? t2.w : t1.w;   hi.w = swp ? t1.w : t2.w;
}

__global__ __launch_bounds__(256)
void permute_ws_benes(const float4* __restrict__ x,
                      float4* __restrict__ out,
                      int nrows)
{
    int t = threadIdx.x;
    int lane = t & 31, warp = t >> 5;
    int row = blockIdx.x * 8 + warp;
    if (row >= nrows) return;

    unsigned rt = (unsigned)d_route[lane];
    int ps1 = rt & 31, ps2 = (rt >> 5) & 31;
    unsigned psel = (rt >> 10) & 1u, pswp = (rt >> 11) & 1u;
    unsigned rn = rt >> 16;
    int ns1 = rn & 31, ns2 = (rn >> 5) & 31;
    unsigned nsel = (rn >> 10) & 1u, nswp = (rn >> 11) & 1u;

    const float4* __restrict__ r = x + (long long)row * 64;
    float4*       __restrict__ o = out + (long long)row * 64;

    float4 v0 = r[lane];        // fully coalesced, row read exactly once
    float4 v1 = r[lane + 32];

    float4 plo, phi, nlo, nhi;
    route_gather(v0, v1, ps1, ps2, psel, pswp, plo, phi);
    route_gather(v0, v1, ns1, ns2, nsel, nswp, nlo, nhi);

    float4 olo, ohi;
    olo.x = plo.x - nlo.x;  olo.y = plo.y - nlo.y;
    olo.z = plo.z - nlo.z;  olo.w = plo.w - nlo.w;
    ohi.x = phi.x - nhi.x;  ohi.y = phi.y - nhi.y;
    ohi.z = phi.z - nhi.z;  ohi.w = phi.w - nhi.w;

    o[lane]      = olo;         // fully coalesced stores
    o[lane + 32] = ohi;
}

extern "C" void kernel_launch(void* const* d_in, const int* in_sizes, int n_in,
                              void* d_out, int out_size)
{
    const float4* x    = (const float4*)d_in[0];
    const float*  Ppos = (const float*)d_in[1];
    const float*  Pneg = (const float*)d_in[2];
    float4*       out  = (float4*)d_out;

    int nrows = out_size / 256;                 // 131072
    int blocks = (nrows + 7) / 8;               // 8 warps per block, 1 row per warp

    route_setup<<<1, 32>>>(Ppos, Pneg);
    permute_ws_benes<<<blocks, 256>>>(x, out, nrows);
}

// round 6
// speedup vs baseline: 1.0142x; 1.0142x over previous
#include <cuda_runtime.h>

// PermuteWeightSharing: out[..., i*16+k] = x[..., p[i]*16+k] - x[..., n[i]*16+k]
// x: (512,16,16,256) fp32 = 131072 rows x 256 floats (64 x 16B chunks, 16 slots of 64B).
//
// R3: one warp per row, row held as v0=chunk[lane], v1=chunk[lane+32].
// The 64-chunk permutation (2 chunks per lane) forms a 2-regular bipartite
// multigraph src-lane -> dst-lane; it decomposes into 2 perfect matchings.
// Pre-select (ALU) at the source puts the matching-0 chunk in r0, matching-1
// in r1; ONE shfl per register per operand then delivers everything:
// 16 shfl/row total (information floor) vs 32 before. Loads/stores stay
// fully coalesced. Routing tables built once by a tiny setup kernel.

#define FULLMASK 0xFFFFFFFFu

__device__ int d_route[32];   // packed per-lane routing (pos in low 16b, neg in high 16b)

// ---------------------------------------------------------------------------
// Setup: decode one-hot perms, 2-color the slot-level routing multigraph
// (edges = 16 out-slots; dst-partner(i) = i^8, src-partner(i) = Pinv[P[i]^8]),
// emit per-lane packed route words.
// ---------------------------------------------------------------------------
__global__ void route_setup(const float* __restrict__ Ppos,
                            const float* __restrict__ Pneg)
{
    __shared__ int P[2][16], Pinv[2][16], col[2][16];
    int t = threadIdx.x;              // 32 threads

    if (t < 32) {
        int o = t >> 4, i = t & 15;
        const float* M = o ? Pneg : Ppos;
        int js = 0;
        #pragma unroll
        for (int j = 0; j < 16; ++j)
            if (M[i * 16 + j] > 0.5f) js = j;
        P[o][i] = js;                 // out slot i sources from in slot js
    }
    __syncthreads();
    if (t < 32) { int o = t >> 4, i = t & 15; Pinv[o][P[o][i]] = i; }
    __syncthreads();

    if (t < 2) {                      // one thread per operand: cycle walk
        int o = t;
        for (int i = 0; i < 16; ++i) col[o][i] = -1;
        for (int st = 0; st < 16; ++st) {
            if (col[o][st] >= 0) continue;
            int e = st, c = 0;
            while (col[o][e] < 0) {
                col[o][e] = c;        // edge e gets color c
                int f = e ^ 8;        // dst partner: opposite color
                col[o][f] = 1 - c;
                e = Pinv[o][P[o][f] ^ 8];   // src partner of f: color c again
            }
        }
    }
    __syncthreads();

    if (t < 32) {
        int l = t, g = l >> 2, k = l & 3;
        unsigned rt = 0;
        #pragma unroll
        for (int o = 0; o < 2; ++o) {
            int ilo = g, ihi = g + 8;
            int c_lo = col[o][ilo];               // colors of lo/hi edges differ
            int i0 = (c_lo == 0) ? ilo : ihi;     // this dst lane's color-0 edge
            int i1 = (c_lo == 0) ? ihi : ilo;
            int src1 = 4 * (P[o][i0] & 7) + k;    // src lane for matching 0
            int src2 = 4 * (P[o][i1] & 7) + k;    // src lane for matching 1
            int swp  = c_lo;                      // 1: matching-0 delivers hi
            int sel  = col[o][Pinv[o][g]];        // 1: this lane's color-0 chunk is v1
            rt |= (unsigned)(src1 | (src2 << 5) | (sel << 10) | (swp << 11)) << (16 * o);
        }
        d_route[l] = (int)rt;
    }
}

// ---------------------------------------------------------------------------
// Main kernel
// ---------------------------------------------------------------------------
__device__ __forceinline__ void route_gather(
    const float4 v0, const float4 v1,
    int s1, int s2, unsigned sel, unsigned swp,
    float4& lo, float4& hi)
{
    float4 r0, r1;                                // source-side pre-select (ALU)
    r0.x = sel ? v1.x : v0.x;   r1.x = sel ? v0.x : v1.x;
    r0.y = sel ? v1.y : v0.y;   r1.y = sel ? v0.y : v1.y;
    r0.z = sel ? v1.z : v0.z;   r1.z = sel ? v0.z : v1.z;
    r0.w = sel ? v1.w : v0.w;   r1.w = sel ? v0.w : v1.w;

    float4 t1, t2;                                // one shfl per register
    t1.x = __shfl_sync(FULLMASK, r0.x, s1);
    t1.y = __shfl_sync(FULLMASK, r0.y, s1);
    t1.z = __shfl_sync(FULLMASK, r0.z, s1);
    t1.w = __shfl_sync(FULLMASK, r0.w, s1);
    t2.x = __shfl_sync(FULLMASK, r1.x, s2);
    t2.y = __shfl_sync(FULLMASK, r1.y, s2);
    t2.z = __shfl_sync(FULLMASK, r1.z, s2);
    t2.w = __shfl_sync(FULLMASK, r1.w, s2);

    lo.x = swp ? t2.x : t1.x;   hi.x = swp ? t1.x : t2.x;   // dst-side post-select
    lo.y = swp ? t2.y : t1.y;   hi.y = swp ? t1.y : t2.y;
    lo.z = swp ? t2.z : t1.z;   hi.z = swp ? t1.z : t2.z;
    lo.w = swp ? t2.w : t1.w;   hi.w = swp ? t1.w : t2.w;
}

__global__ __launch_bounds__(256)
void permute_ws_benes(const float4* __restrict__ x,
                      float4* __restrict__ out,
                      int nrows)
{
    int t = threadIdx.x;
    int lane = t & 31, warp = t >> 5;
    int row = blockIdx.x * 8 + warp;
    if (row >= nrows) return;

    unsigned rt = (unsigned)d_route[lane];
    int ps1 = rt & 31, ps2 = (rt >> 5) & 31;
    unsigned psel = (rt >> 10) & 1u, pswp = (rt >> 11) & 1u;
    unsigned rn = rt >> 16;
    int ns1 = rn & 31, ns2 = (rn >> 5) & 31;
    unsigned nsel = (rn >> 10) & 1u, nswp = (rn >> 11) & 1u;

    const float4* __restrict__ r = x + (long long)row * 64;
    float4*       __restrict__ o = out + (long long)row * 64;

    float4 v0 = r[lane];        // fully coalesced, row read exactly once
    float4 v1 = r[lane + 32];

    float4 plo, phi, nlo, nhi;
    route_gather(v0, v1, ps1, ps2, psel, pswp, plo, phi);
    route_gather(v0, v1, ns1, ns2, nsel, nswp, nlo, nhi);

    float4 olo, ohi;
    olo.x = plo.x - nlo.x;  olo.y = plo.y - nlo.y;
    olo.z = plo.z - nlo.z;  olo.w = plo.w - nlo.w;
    ohi.x = phi.x - nhi.x;  ohi.y = phi.y - nhi.y;
    ohi.z = phi.z - nhi.z;  ohi.w = phi.w - nhi.w;

    o[lane]      = olo;         // fully coalesced stores
    o[lane + 32] = ohi;
}

extern "C" void kernel_launch(void* const* d_in, const int* in_sizes, int n_in,
                              void* d_out, int out_size)
{
    const float4* x    = (const float4*)d_in[0];
    const float*  Ppos = (const float*)d_in[1];
    const float*  Pneg = (const float*)d_in[2];
    float4*       out  = (float4*)d_out;

    int nrows = out_size / 256;                 // 131072
    int blocks = (nrows + 7) / 8;               // 8 warps per block, 1 row per warp

    route_setup<<<1, 32>>>(Ppos, Pneg);
    permute_ws_benes<<<blocks, 256>>>(x, out, nrows);
}